// round 15
// baseline (speedup 1.0000x reference)
#include <cuda_runtime.h>
#include <math.h>

#define TMAX 2048
// element layout (floats): mu[0..127], logw at 128, pad to 136, Sigma 128x128
#define ELT 16520
#define MU_OFF 0
#define W_OFF 128
#define SIG_OFF 136
#define STR 196         // stride of fused 64x193 workspace [S(64) | W(128) | d(1)] + pad
#define D_COL 192
#define STRZ 132        // stride of z-only workspace [S(64) | Wq(64) | d(1)] + pad
#define D_COLZ 128
#define NT 256
#define LOG2PI 1.8378770664093453f

// ---------------- device scratch (static; no allocations) ----------------
__device__ float gTvar[128 * 128];
__device__ float gBufA[(size_t)TMAX * ELT];
__device__ float gBufB[(size_t)(TMAX / 2) * ELT];
__device__ float gEG[ELT];   // bare transition joint
__device__ float gEP[ELT];   // prior N(0,I) (degenerate in x)
__device__ float gEI[ELT];   // eInit = compose(gEP, gEG)
__device__ float gFin[ELT];  // final element (z-side only valid)

// ---------------- Tvar = tcho^T @ tcho (one block) ----------------
__global__ void __launch_bounds__(NT) prek_kernel(const float* __restrict__ tcho) {
    extern __shared__ float s[];   // 128*128
    int tid = threadIdx.x;
    for (int i = tid; i < 128 * 128; i += NT) s[i] = tcho[i];
    __syncthreads();
    int i0 = (tid >> 4) * 8, j0 = (tid & 15) * 8;
    float acc[8][8];
#pragma unroll
    for (int q = 0; q < 8; q++)
#pragma unroll
        for (int w = 0; w < 8; w++) acc[q][w] = 0.f;
    for (int k = 0; k < 128; ++k) {
        const float* row = s + (k << 7);
        float a[8], b[8];
#pragma unroll
        for (int q = 0; q < 8; q++) a[q] = row[i0 + q];
#pragma unroll
        for (int w = 0; w < 8; w++) b[w] = row[j0 + w];
#pragma unroll
        for (int q = 0; q < 8; q++)
#pragma unroll
            for (int w = 0; w < 8; w++) acc[q][w] += a[q] * b[w];
    }
#pragma unroll
    for (int q = 0; q < 8; q++)
#pragma unroll
        for (int w = 0; w < 8; w++) gTvar[(i0 + q) * 128 + j0 + w] = acc[q][w];
}

// ---------------- boundary elements ----------------
__global__ void __launch_bounds__(NT) einit_kernel(const float* __restrict__ tmu) {
    int tid = threadIdx.x;
    for (int i = tid; i < 128 * 128; i += NT) {
        gEG[SIG_OFF + i] = gTvar[i];
        int r = i >> 7, c = i & 127;
        gEP[SIG_OFF + i] = (r == c && r >= 64) ? 1.f : 0.f;
    }
    if (tid < 128) { gEG[MU_OFF + tid] = tmu[tid]; gEP[MU_OFF + tid] = 0.f; }
    if (tid == 0) { gEG[W_OFF] = 0.f; gEP[W_OFF] = 0.f; }
}

// ---------------- warp-0 panel factorization (rows c0..63 x cols c0..c0+15) ----------------
// LU in registers (warp-sync): multipliers below diag, U on/above. Then builds
// L11^{-1} straight from the register panel via shuffles (no smem latency chain).
template<int STRIDE>
__device__ __forceinline__ void panel_factor(float* sA, float* sL11inv, int p, int lane) {
    int c0 = p << 4;
    int nrp = 64 - c0;
    int r0 = c0 + lane, r1 = r0 + 32;
    bool h0 = lane < nrp, h1 = lane + 32 < nrp;
    float a0[16], a1[16];
#pragma unroll
    for (int k = 0; k < 16; ++k) {
        a0[k] = h0 ? sA[r0 * STRIDE + c0 + k] : 0.f;
        a1[k] = h1 ? sA[r1 * STRIDE + c0 + k] : 0.f;
    }
#pragma unroll
    for (int jj = 0; jj < 16; ++jj) {
        float bk[16];
#pragma unroll
        for (int k = 0; k < 16; ++k) bk[k] = __shfl_sync(~0u, a0[k], jj);
        float rp = __frcp_rn(bk[jj]);
        if (h0 && lane > jj) {
            float m = a0[jj] * rp; a0[jj] = m;
#pragma unroll
            for (int k = 0; k < 16; ++k) if (k > jj) a0[k] -= m * bk[k];
        }
        if (h1) {
            float m = a1[jj] * rp; a1[jj] = m;
#pragma unroll
            for (int k = 0; k < 16; ++k) if (k > jj) a1[k] -= m * bk[k];
        }
    }
#pragma unroll
    for (int k = 0; k < 16; ++k) {
        if (h0) sA[r0 * STRIDE + c0 + k] = a0[k];
        if (h1) sA[r1 * STRIDE + c0 + k] = a1[k];
    }
    // ---- L11^{-1} from registers: lane (c = lane&15) computes column c ----
    int c = lane & 15;
    float x[16];
#pragma unroll
    for (int j = 0; j < 16; ++j) {
        float s = 0.f;
#pragma unroll
        for (int k = 0; k < 16; ++k) {
            float Ljk = __shfl_sync(~0u, a0[k], j);
            if (k < j) s += Ljk * x[k];
        }
        x[j] = (j == c) ? 1.f : ((j < c) ? 0.f : -s);
    }
    if (lane < 16)
#pragma unroll
        for (int j = 0; j < 16; ++j) sL11inv[j * 16 + c] = x[j];
}

// 4-row rank-16 trailing update of one float4 column group
template<int STRIDE>
__device__ __forceinline__ void gemm2_item(float* sA, int c0, int r, int col) {
    float4 a0 = *(const float4*)(sA + (r + 0) * STRIDE + col);
    float4 a1 = *(const float4*)(sA + (r + 1) * STRIDE + col);
    float4 a2 = *(const float4*)(sA + (r + 2) * STRIDE + col);
    float4 a3 = *(const float4*)(sA + (r + 3) * STRIDE + col);
#pragma unroll 1
    for (int k = 0; k < 16; ++k) {
        const float4 b = *(const float4*)(sA + (c0 + k) * STRIDE + col);
        float f0 = sA[(r + 0) * STRIDE + c0 + k];
        float f1 = sA[(r + 1) * STRIDE + c0 + k];
        float f2 = sA[(r + 2) * STRIDE + c0 + k];
        float f3 = sA[(r + 3) * STRIDE + c0 + k];
        a0.x -= f0 * b.x; a0.y -= f0 * b.y; a0.z -= f0 * b.z; a0.w -= f0 * b.w;
        a1.x -= f1 * b.x; a1.y -= f1 * b.y; a1.z -= f1 * b.z; a1.w -= f1 * b.w;
        a2.x -= f2 * b.x; a2.y -= f2 * b.y; a2.z -= f2 * b.z; a2.w -= f2 * b.w;
        a3.x -= f3 * b.x; a3.y -= f3 * b.y; a3.z -= f3 * b.z; a3.w -= f3 * b.w;
    }
    *(float4*)(sA + (r + 0) * STRIDE + col) = a0;
    *(float4*)(sA + (r + 1) * STRIDE + col) = a1;
    *(float4*)(sA + (r + 2) * STRIDE + col) = a2;
    *(float4*)(sA + (r + 3) * STRIDE + col) = a3;
}

// ---------------- lookahead blocked LU on fused [S | RHS] (64 x NCOLS) ----------------
// Panel factor of p+1 runs CONCURRENTLY with the bulk trailing update of panel p:
// the only exposed serial panel work is panel 0. On exit: diag = pivots, RHS
// columns hold L^{-1} * RHS. Bit-identical to the non-lookahead schedule.
template<int STRIDE, int NCOLS>
__device__ __forceinline__ void factor_la(float* sA, float* sL11inv, int tid, int bs) {
    const int gTot = (NCOLS + 3) >> 2;
    int wid = tid >> 5, lane = tid & 31;
    if (wid == 0) panel_factor<STRIDE>(sA, sL11inv, 0, lane);
    __syncthreads();
#pragma unroll 1
    for (int p = 0; p < 4; ++p) {
        int c0 = p << 4;
        int g0 = (c0 + 16) >> 2;
        int tw = gTot - g0;
        // ---- GEMM1 (TRSM): U12 = L11inv @ A12(original), 4 rows/thread ----
        float4 acc1[4];
        int i4 = 0, col1 = 0;
        bool act1 = (tid < 4 * tw);
        if (act1) {
            i4 = tid / tw;
            col1 = (g0 + (tid - i4 * tw)) << 2;
#pragma unroll
            for (int q = 0; q < 4; ++q) acc1[q] = make_float4(0.f, 0.f, 0.f, 0.f);
#pragma unroll 1
            for (int k = 0; k < 16; ++k) {
                const float4 b = *(const float4*)(sA + (c0 + k) * STRIDE + col1);
#pragma unroll
                for (int q = 0; q < 4; ++q) {
                    float f = sL11inv[(i4 * 4 + q) * 16 + k];
                    acc1[q].x += f * b.x; acc1[q].y += f * b.y;
                    acc1[q].z += f * b.z; acc1[q].w += f * b.w;
                }
            }
        }
        __syncthreads();
        if (act1) {
#pragma unroll
            for (int q = 0; q < 4; ++q)
                *(float4*)(sA + (c0 + i4 * 4 + q) * STRIDE + col1) = acc1[q];
        }
        __syncthreads();
        if (p < 3) {
            int rs = c0 + 16, nq = (64 - rs) >> 2;
            // ---- GEMM2-critical: only next panel's columns [c0+16, c0+32) ----
            for (int m = tid; m < nq * 4; m += bs) {
                int q4 = m >> 2, gg = m & 3;
                gemm2_item<STRIDE>(sA, c0, rs + q4 * 4, (g0 + gg) << 2);
            }
            __syncthreads();
            // ---- CONCURRENT: warp 0 factors panel p+1; others do GEMM2-rest ----
            if (wid == 0) {
                panel_factor<STRIDE>(sA, sL11inv, p + 1, lane);
            } else {
                int twr = tw - 4;
                for (int m = tid - 32; m < nq * twr; m += bs - 32) {
                    int q4 = m / twr, gg = m - q4 * twr;
                    gemm2_item<STRIDE>(sA, c0, rs + q4 * 4, (g0 + 4 + gg) << 2);
                }
            }
            __syncthreads();
        }
    }
}

// ---------------- shared epilogue: precise inv, scaled RHS, score pieces ----------------
__device__ __forceinline__ void pivot_epilogue2(const float* sA, int stride, int dcol,
                                                float* sInv, float* sTv, float* sRed, int tid) {
    float val = 0.f;
    if (tid < 64) {
        float piv = sA[tid * stride + tid];
        float iv = 1.0f / piv;
        sInv[tid] = iv;
        float y = sA[tid * stride + dcol];
        sTv[tid] = y * iv;
        val = logf(piv) + y * y * iv;
    }
    for (int o = 16; o > 0; o >>= 1) val += __shfl_down_sync(~0u, val, o);
    if (tid == 0) sRed[0] = val;
    if (tid == 32) sRed[1] = val;
}

// ---------------- Schur 32x32 warp tile: thread = 4 rows x 8 cols ----------------
__device__ __forceinline__ void schur_tile32(const float* sA, const float* sInv, int stride,
                                             int wb, int i0, int j0, int lane,
                                             float acc[4][8]) {
    int ra = wb + i0 + (lane & 7) * 4;
    int cb = wb + j0 + (lane >> 3) * 8;
#pragma unroll
    for (int q = 0; q < 4; q++)
#pragma unroll
        for (int w = 0; w < 8; w++) acc[q][w] = 0.f;
#pragma unroll 1
    for (int k = 0; k < 64; ++k) {
        const float* row = sA + k * stride;
        float iv = sInv[k];
        float4 av = *(const float4*)(row + ra);
        float4 b0 = *(const float4*)(row + cb);
        float4 b1 = *(const float4*)(row + cb + 4);
        float a[4] = {av.x * iv, av.y * iv, av.z * iv, av.w * iv};
        float b[8] = {b0.x, b0.y, b0.z, b0.w, b1.x, b1.y, b1.z, b1.w};
#pragma unroll
        for (int q = 0; q < 4; q++)
#pragma unroll
            for (int w = 0; w < 8; w++) acc[q][w] += a[q] * b[w];
    }
}

// ---------------- leaf: h_t = N(x; im_t, D_t) * N([x;z]; tmu, Tvar) ----------------
__global__ void __launch_bounds__(NT, 3) leaf_kernel(const int* __restrict__ sent,
                                                     const float* __restrict__ memb,
                                                     const float* __restrict__ cemb,
                                                     const float* __restrict__ tmu) {
    extern __shared__ float sm[];
    float* sA = sm;                     // 64 x STR
    float* sL11inv = sA + 64 * STR;     // 16 x 16
    float* sInv = sL11inv + 256;
    float* sTv = sInv + 64;
    float* sRed = sTv + 64;
    int t = blockIdx.x, tid = threadIdx.x;
    int wid = tid >> 5, lane = tid & 31;
    int tok = sent[t];
    for (int idx = tid; idx < 64 * 128; idx += NT) {
        int r = idx >> 7, c = idx & 127;
        float v = gTvar[r * 128 + c];
        sA[r * STR + 64 + c] = v;              // W = Tvar rows 0..63 (full 128 cols)
        if (c < 64) sA[r * STR + c] = v;       // S = Saa
    }
    __syncthreads();
    if (tid < 64) {
        float ch = cemb[tok * 64 + tid];
        sA[tid * STR + tid] += ch * ch;                           // S = Saa + D
        sA[tid * STR + D_COL] = memb[tok * 64 + tid] - tmu[tid];  // d = im - mu_a
        sA[tid * STR + 193] = 0.f; sA[tid * STR + 194] = 0.f; sA[tid * STR + 195] = 0.f;
    }
    __syncthreads();
    factor_la<STR, 193>(sA, sL11inv, tid, NT);
    pivot_epilogue2(sA, STR, D_COL, sInv, sTv, sRed, tid);
    __syncthreads();
    float* eo = gBufA + (size_t)t * ELT;
    if (tid < 128) {      // mu' = tmu + W^T D^-1 y
        float a = 0.f;
        for (int k = 0; k < 64; ++k) a += sA[k * STR + 64 + tid] * sTv[k];
        eo[MU_OFF + tid] = tmu[tid] + a;
    }
    if (tid == 128) eo[W_OFF] = -0.5f * (64.f * LOG2PI + sRed[0] + sRed[1]);

    // Sigma' = Tvar - W^T D^-1 W : 16 tiles of 32x32
    for (int tt = wid; tt < 16; tt += 8) {
        int i0 = (tt >> 2) * 32, j0 = (tt & 3) * 32;
        float acc[4][8];
        schur_tile32(sA, sInv, STR, 64, i0, j0, lane, acc);
        int rbase = i0 + (lane & 7) * 4;
        int cb = j0 + (lane >> 3) * 8;
#pragma unroll
        for (int q = 0; q < 4; ++q) {
            int r = rbase + q;
            float4 b0 = *(const float4*)(gTvar + r * 128 + cb);
            float4 b1 = *(const float4*)(gTvar + r * 128 + cb + 4);
            float4 v0, v1;
            v0.x = b0.x - acc[q][0]; v0.y = b0.y - acc[q][1];
            v0.z = b0.z - acc[q][2]; v0.w = b0.w - acc[q][3];
            v1.x = b1.x - acc[q][4]; v1.y = b1.y - acc[q][5];
            v1.z = b1.z - acc[q][6]; v1.w = b1.w - acc[q][7];
            *(float4*)(eo + SIG_OFF + r * 128 + cb) = v0;
            *(float4*)(eo + SIG_OFF + r * 128 + cb + 4) = v1;
        }
    }
}

// ---------------- shared compose body ----------------
__device__ __forceinline__ void compose_body(const float* __restrict__ e1,
                                             const float* __restrict__ e2,
                                             float* __restrict__ eo,
                                             float* sm, int tid, int bs) {
    float* sA = sm;
    float* sL11inv = sA + 64 * STR;
    float* sInv = sL11inv + 256;
    float* sTv = sInv + 64;
    float* sRed = sTv + 64;
    int wid = tid >> 5, lane = tid & 31, nw = bs >> 5;
    const float* S1 = e1 + SIG_OFF;
    const float* S2 = e2 + SIG_OFF;
    for (int idx = tid; idx < 64 * 64; idx += bs) {
        int r = idx >> 6, c = idx & 63;
        sA[r * STR + c] = S1[(64 + r) * 128 + 64 + c] + S2[r * 128 + c];  // P_yy + Q_yy
        sA[r * STR + 64 + c] = S1[(64 + r) * 128 + c];                     // P_yx
        sA[r * STR + 128 + c] = S2[r * 128 + 64 + c];                      // Q_yz
    }
    if (tid < 64) {
        sA[tid * STR + D_COL] = e1[MU_OFF + 64 + tid] - e2[MU_OFF + tid];  // d
        sA[tid * STR + 193] = 0.f; sA[tid * STR + 194] = 0.f; sA[tid * STR + 195] = 0.f;
    }
    __syncthreads();
    factor_la<STR, 193>(sA, sL11inv, tid, bs);
    pivot_epilogue2(sA, STR, D_COL, sInv, sTv, sRed, tid);
    __syncthreads();
    if (tid < 64) {        // mu'_x = m1_x - W_P^T D^-1 y
        float a = 0.f;
        for (int k = 0; k < 64; ++k) a += sA[k * STR + 64 + tid] * sTv[k];
        eo[MU_OFF + tid] = e1[MU_OFF + tid] - a;
    } else if (tid < 128) { // mu'_z = m2_z + W_Q^T D^-1 y
        int cc = tid - 64;
        float a = 0.f;
        for (int k = 0; k < 64; ++k) a += sA[k * STR + 128 + cc] * sTv[k];
        eo[MU_OFF + tid] = e2[MU_OFF + 64 + cc] + a;
    }
    if (tid == 128)
        eo[W_OFF] = e1[W_OFF] + e2[W_OFF] - 0.5f * (64.f * LOG2PI + sRed[0] + sRed[1]);

    // Sigma' full 128x128: 16 tiles of 32x32 (each tile lies in one quadrant)
    for (int tt = wid; tt < 16; tt += nw) {
        int i0 = (tt >> 2) * 32, j0 = (tt & 3) * 32;
        float acc[4][8];
        schur_tile32(sA, sInv, STR, 64, i0, j0, lane, acc);
        int rbase = i0 + (lane & 7) * 4;
        int cb = j0 + (lane >> 3) * 8;
        bool rLow = (i0 < 64), cLow = (j0 < 64);
#pragma unroll
        for (int q = 0; q < 4; ++q) {
            int r = rbase + q;
            float4 v0, v1;
            if (rLow && cLow) {
                float4 b0 = *(const float4*)(S1 + r * 128 + cb);
                float4 b1 = *(const float4*)(S1 + r * 128 + cb + 4);
                v0.x = b0.x - acc[q][0]; v0.y = b0.y - acc[q][1];
                v0.z = b0.z - acc[q][2]; v0.w = b0.w - acc[q][3];
                v1.x = b1.x - acc[q][4]; v1.y = b1.y - acc[q][5];
                v1.z = b1.z - acc[q][6]; v1.w = b1.w - acc[q][7];
            } else if (!rLow && !cLow) {
                float4 b0 = *(const float4*)(S2 + r * 128 + cb);
                float4 b1 = *(const float4*)(S2 + r * 128 + cb + 4);
                v0.x = b0.x - acc[q][0]; v0.y = b0.y - acc[q][1];
                v0.z = b0.z - acc[q][2]; v0.w = b0.w - acc[q][3];
                v1.x = b1.x - acc[q][4]; v1.y = b1.y - acc[q][5];
                v1.z = b1.z - acc[q][6]; v1.w = b1.w - acc[q][7];
            } else {
                v0.x = acc[q][0]; v0.y = acc[q][1]; v0.z = acc[q][2]; v0.w = acc[q][3];
                v1.x = acc[q][4]; v1.y = acc[q][5]; v1.z = acc[q][6]; v1.w = acc[q][7];
            }
            *(float4*)(eo + SIG_OFF + r * 128 + cb) = v0;
            *(float4*)(eo + SIG_OFF + r * 128 + cb + 4) = v1;
        }
    }
}

// wide levels: 256 threads, min 3 CTAs/SM
__global__ void __launch_bounds__(NT, 3) compose_wide_kernel(const float* __restrict__ e1b,
                                                             const float* __restrict__ e2b,
                                                             float* __restrict__ eob) {
    extern __shared__ float sm[];
    const float* e1 = e1b + (size_t)blockIdx.x * (size_t)(2 * ELT);
    const float* e2 = e1 + ELT;
    float* eo = eob + (size_t)blockIdx.x * (size_t)ELT;
    compose_body(e1, e2, eo, sm, threadIdx.x, NT);
}

// tail levels: 512 threads (occupancy irrelevant, latency matters)
__global__ void __launch_bounds__(512) compose_tail_kernel(const float* __restrict__ e1b,
                                                           const float* __restrict__ e2b,
                                                           float* __restrict__ eob,
                                                           long sIn, long sOut) {
    extern __shared__ float sm[];
    const float* e1 = e1b + (size_t)blockIdx.x * (size_t)sIn;
    const float* e2 = e2b + (size_t)blockIdx.x * (size_t)sIn;
    float* eo = eob + (size_t)blockIdx.x * (size_t)sOut;
    compose_body(e1, e2, eo, sm, threadIdx.x, blockDim.x);
}

// ---------------- z-only final compose: only logw, mu_z, Sigma_zz of eI (.) root ----------------
__global__ void __launch_bounds__(512) compose_z_kernel(const float* __restrict__ e1,
                                                        const float* __restrict__ e2,
                                                        float* __restrict__ eo) {
    extern __shared__ float sm[];
    float* sA = sm;                      // 64 x STRZ : [S(64) | Wq(64) | d | pad]
    float* sL11inv = sA + 64 * STRZ;
    float* sInv = sL11inv + 256;
    float* sTv = sInv + 64;
    float* sRed = sTv + 64;
    int tid = threadIdx.x, bs = blockDim.x;
    int wid = tid >> 5, lane = tid & 31, nw = bs >> 5;
    const float* S1 = e1 + SIG_OFF;
    const float* S2 = e2 + SIG_OFF;
    for (int idx = tid; idx < 64 * 64; idx += bs) {
        int r = idx >> 6, c = idx & 63;
        sA[r * STRZ + c] = S1[(64 + r) * 128 + 64 + c] + S2[r * 128 + c];  // P_yy + Q_yy
        sA[r * STRZ + 64 + c] = S2[r * 128 + 64 + c];                       // Q_yz
    }
    if (tid < 64) {
        sA[tid * STRZ + D_COLZ] = e1[MU_OFF + 64 + tid] - e2[MU_OFF + tid];
        sA[tid * STRZ + 129] = 0.f; sA[tid * STRZ + 130] = 0.f; sA[tid * STRZ + 131] = 0.f;
    }
    __syncthreads();
    factor_la<STRZ, 129>(sA, sL11inv, tid, bs);
    pivot_epilogue2(sA, STRZ, D_COLZ, sInv, sTv, sRed, tid);
    __syncthreads();
    if (tid < 64) {        // mu'_z = m2_z + W_Q^T D^-1 y
        float a = 0.f;
        for (int k = 0; k < 64; ++k) a += sA[k * STRZ + 64 + tid] * sTv[k];
        eo[MU_OFF + 64 + tid] = e2[MU_OFF + 64 + tid] + a;
    }
    if (tid == 64)
        eo[W_OFF] = e1[W_OFF] + e2[W_OFF] - 0.5f * (64.f * LOG2PI + sRed[0] + sRed[1]);
    // Sigma'_zz = S2_zz - Wq^T D^-1 Wq  (64x64): 4 tiles of 32x32
    for (int tt = wid; tt < 4; tt += nw) {
        int i0 = (tt >> 1) * 32, j0 = (tt & 1) * 32;
        float acc[4][8];
        schur_tile32(sA, sInv, STRZ, 64, i0, j0, lane, acc);
        int rbase = i0 + (lane & 7) * 4;
        int cb = j0 + (lane >> 3) * 8;
#pragma unroll
        for (int q = 0; q < 4; ++q) {
            int r = rbase + q;
            float4 b0 = *(const float4*)(S2 + (64 + r) * 128 + 64 + cb);
            float4 b1 = *(const float4*)(S2 + (64 + r) * 128 + 64 + cb + 4);
            float4 v0, v1;
            v0.x = b0.x - acc[q][0]; v0.y = b0.y - acc[q][1];
            v0.z = b0.z - acc[q][2]; v0.w = b0.w - acc[q][3];
            v1.x = b1.x - acc[q][4]; v1.y = b1.y - acc[q][5];
            v1.z = b1.z - acc[q][6]; v1.w = b1.w - acc[q][7];
            *(float4*)(eo + SIG_OFF + (64 + r) * 128 + 64 + cb) = v0;
            *(float4*)(eo + SIG_OFF + (64 + r) * 128 + 64 + cb + 4) = v1;
        }
    }
}

// ---------------- decode: 50 independent scores via the same fast factor ----------------
#define DSTR 68
__global__ void __launch_bounds__(NT) decode_kernel(const float* __restrict__ omu,
                                                    const float* __restrict__ ocho,
                                                    float* __restrict__ out, int nlab) {
    extern __shared__ float sm[];
    float* sA = sm;                    // 64 x DSTR, cols: S(64) | z(1) | pad
    float* sL11inv = sA + 64 * DSTR;
    float* sRed = sL11inv + 256;
    int l = blockIdx.x, tid = threadIdx.x;
    if (l >= nlab) return;
    for (int idx = tid; idx < 64 * 64; idx += NT) {
        int r = idx >> 6, c = idx & 63;
        sA[r * DSTR + c] = gFin[SIG_OFF + (64 + r) * 128 + 64 + c];
    }
    __syncthreads();
    if (tid < 64) {
        float oc = ocho[l * 64 + tid];
        sA[tid * DSTR + tid] += oc * oc;
        sA[tid * DSTR + 64] = gFin[MU_OFF + 64 + tid] - omu[l * 64 + tid];
        sA[tid * DSTR + 65] = 0.f; sA[tid * DSTR + 66] = 0.f; sA[tid * DSTR + 67] = 0.f;
    }
    __syncthreads();
    factor_la<DSTR, 65>(sA, sL11inv, tid, NT);
    float val = 0.f;
    if (tid < 64) {
        float piv = sA[tid * DSTR + tid];
        float y = sA[tid * DSTR + 64];
        val = logf(piv) + y * y / piv;
    }
    for (int o = 16; o > 0; o >>= 1) val += __shfl_down_sync(~0u, val, o);
    if (tid == 0) sRed[0] = val;
    if (tid == 32) sRed[1] = val;
    __syncthreads();
    if (tid == 0) out[l] = gFin[W_OFF] - 0.5f * (64.f * LOG2PI + sRed[0] + sRed[1]);
}

// ---------------- launch ----------------
static const int CSM  = (64 * STR + 256 + 64 + 64 + 8) * 4;
static const int CSMZ = (64 * STRZ + 256 + 64 + 64 + 8) * 4;
static const int DSM  = (64 * DSTR + 256 + 8) * 4;

extern "C" void kernel_launch(void* const* d_in, const int* in_sizes, int n_in,
                              void* d_out, int out_size) {
    const int*   sent = (const int*)d_in[0];
    const float* memb = (const float*)d_in[2];
    const float* cemb = (const float*)d_in[3];
    const float* tmu  = (const float*)d_in[4];
    const float* tcho = (const float*)d_in[5];
    const float* omu  = (const float*)d_in[6];
    const float* ocho = (const float*)d_in[7];
    float* out = (float*)d_out;

    int n = in_sizes[0];
    if (n > TMAX) n = TMAX;
    if (n < 1) n = 1;
    int nlab = out_size;
    if (nlab <= 0) nlab = in_sizes[6] / 64;

    cudaFuncSetAttribute(prek_kernel, cudaFuncAttributeMaxDynamicSharedMemorySize, 128 * 128 * 4);
    cudaFuncSetAttribute(leaf_kernel, cudaFuncAttributeMaxDynamicSharedMemorySize, CSM);
    cudaFuncSetAttribute(compose_wide_kernel, cudaFuncAttributeMaxDynamicSharedMemorySize, CSM);
    cudaFuncSetAttribute(compose_tail_kernel, cudaFuncAttributeMaxDynamicSharedMemorySize, CSM);
    cudaFuncSetAttribute(compose_z_kernel, cudaFuncAttributeMaxDynamicSharedMemorySize, CSMZ);
    cudaFuncSetAttribute(decode_kernel, cudaFuncAttributeMaxDynamicSharedMemorySize, DSM);

    float *bufA, *bufB, *eP, *eG, *eI, *fin;
    cudaGetSymbolAddress((void**)&bufA, gBufA);
    cudaGetSymbolAddress((void**)&bufB, gBufB);
    cudaGetSymbolAddress((void**)&eP, gEP);
    cudaGetSymbolAddress((void**)&eG, gEG);
    cudaGetSymbolAddress((void**)&eI, gEI);
    cudaGetSymbolAddress((void**)&fin, gFin);

    prek_kernel<<<1, NT, 128 * 128 * 4>>>(tcho);
    einit_kernel<<<1, NT>>>(tmu);
    compose_tail_kernel<<<1, 512, CSM>>>(eP, eG, eI, 0, 0);    // eInit = prior (.) joint
    leaf_kernel<<<n, NT, CSM>>>(sent, memb, cemb, tmu);

    float* src = bufA;
    float* dst = bufB;
    int m = n;
    while (m > 1) {
        int nc = m >> 1;
        if (nc > 148)
            compose_wide_kernel<<<nc, NT, CSM>>>(src, src + ELT, dst);
        else
            compose_tail_kernel<<<nc, 512, CSM>>>(src, src + ELT, dst,
                                                  (long)(2 * ELT), (long)ELT);
        if (m & 1)
            cudaMemcpyAsync(dst + (size_t)nc * ELT, src + (size_t)(m - 1) * ELT,
                            (size_t)ELT * sizeof(float), cudaMemcpyDeviceToDevice);
        m = (m + 1) >> 1;
        float* tp = src; src = dst; dst = tp;
    }
    compose_z_kernel<<<1, 512, CSMZ>>>(eI, src, fin);
    decode_kernel<<<nlab, NT, DSM>>>(omu, ocho, out, nlab);
}

// round 16
// speedup vs baseline: 1.1459x; 1.1459x over previous
#include <cuda_runtime.h>
#include <math.h>

#define TMAX 2048
// element layout (floats): mu[0..127], logw at 128, pad to 136, Sigma 128x128
#define ELT 16520
#define MU_OFF 0
#define W_OFF 128
#define SIG_OFF 136
#define STR 196         // stride of fused 64x193 workspace [S(64) | W(128) | d(1)] + pad
#define D_COL 192
#define STRZ 132        // stride of z-only workspace [S(64) | Wq(64) | d(1)] + pad
#define D_COLZ 128
#define NT 256
#define LOG2PI 1.8378770664093453f

// ---------------- device scratch (static; no allocations) ----------------
__device__ float gTvar[128 * 128];
__device__ float gBufA[(size_t)TMAX * ELT];
__device__ float gBufB[(size_t)(TMAX / 2) * ELT];
__device__ float gEG[ELT];   // bare transition joint
__device__ float gEP[ELT];   // prior N(0,I) (degenerate in x)
__device__ float gEI[ELT];   // eInit = compose(gEP, gEG)
__device__ float gFin[ELT];  // final element (z-side only valid)

// ---------------- Tvar = tcho^T @ tcho (one block) ----------------
__global__ void __launch_bounds__(NT) prek_kernel(const float* __restrict__ tcho) {
    extern __shared__ float s[];   // 128*128
    int tid = threadIdx.x;
    for (int i = tid; i < 128 * 128; i += NT) s[i] = tcho[i];
    __syncthreads();
    int i0 = (tid >> 4) * 8, j0 = (tid & 15) * 8;
    float acc[8][8];
#pragma unroll
    for (int q = 0; q < 8; q++)
#pragma unroll
        for (int w = 0; w < 8; w++) acc[q][w] = 0.f;
    for (int k = 0; k < 128; ++k) {
        const float* row = s + (k << 7);
        float a[8], b[8];
#pragma unroll
        for (int q = 0; q < 8; q++) a[q] = row[i0 + q];
#pragma unroll
        for (int w = 0; w < 8; w++) b[w] = row[j0 + w];
#pragma unroll
        for (int q = 0; q < 8; q++)
#pragma unroll
            for (int w = 0; w < 8; w++) acc[q][w] += a[q] * b[w];
    }
#pragma unroll
    for (int q = 0; q < 8; q++)
#pragma unroll
        for (int w = 0; w < 8; w++) gTvar[(i0 + q) * 128 + j0 + w] = acc[q][w];
}

// ---------------- boundary elements ----------------
__global__ void __launch_bounds__(NT) einit_kernel(const float* __restrict__ tmu) {
    int tid = threadIdx.x;
    for (int i = tid; i < 128 * 128; i += NT) {
        gEG[SIG_OFF + i] = gTvar[i];
        int r = i >> 7, c = i & 127;
        gEP[SIG_OFF + i] = (r == c && r >= 64) ? 1.f : 0.f;
    }
    if (tid < 128) { gEG[MU_OFF + tid] = tmu[tid]; gEP[MU_OFF + tid] = 0.f; }
    if (tid == 0) { gEG[W_OFF] = 0.f; gEP[W_OFF] = 0.f; }
}

// ---------------- fast blocked LU on fused [S | RHS] (64 x NCOLS) ----------------
// Right-looking, panel=16. Warp 0 factors each 64x16 panel in registers (warp-sync),
// builds L11^{-1}; TRSM (GEMM1) computes U12 into registers from UNMODIFIED A12
// (4 rows per thread, one op/thread), writes back after a barrier; GEMM2 does the
// rank-16 trailing update with 4 rows per thread (b reused across rows).
// On exit: diag = pivots, RHS columns hold L^{-1} * RHS.
template<int STRIDE, int NCOLS>
__device__ __forceinline__ void factor_fast(float* sA, float* sL11inv, int tid, int bs) {
    const int gTot = (NCOLS + 3) >> 2;
    int wid = tid >> 5, lane = tid & 31;
#pragma unroll 1
    for (int p = 0; p < 4; ++p) {
        int c0 = p << 4;
        int g0 = (c0 + 16) >> 2;
        int tw = gTot - g0;
        if (wid == 0) {
            // ---- panel factorization in registers (warp-sync) ----
            int nrp = 64 - c0;
            int r0 = c0 + lane, r1 = r0 + 32;
            bool h0 = lane < nrp, h1 = lane + 32 < nrp;
            float a0[16], a1[16];
#pragma unroll
            for (int k = 0; k < 16; ++k) {
                a0[k] = h0 ? sA[r0 * STRIDE + c0 + k] : 0.f;
                a1[k] = h1 ? sA[r1 * STRIDE + c0 + k] : 0.f;
            }
#pragma unroll
            for (int jj = 0; jj < 16; ++jj) {
                float bk[16];
#pragma unroll
                for (int k = 0; k < 16; ++k) bk[k] = __shfl_sync(~0u, a0[k], jj);
                float rp = __frcp_rn(bk[jj]);
                if (h0 && lane > jj) {
                    float m = a0[jj] * rp; a0[jj] = m;
#pragma unroll
                    for (int k = 0; k < 16; ++k) if (k > jj) a0[k] -= m * bk[k];
                }
                if (h1) {
                    float m = a1[jj] * rp; a1[jj] = m;
#pragma unroll
                    for (int k = 0; k < 16; ++k) if (k > jj) a1[k] -= m * bk[k];
                }
            }
#pragma unroll
            for (int k = 0; k < 16; ++k) {
                if (h0) sA[r0 * STRIDE + c0 + k] = a0[k];
                if (h1) sA[r1 * STRIDE + c0 + k] = a1[k];
            }
            __syncwarp();
            // ---- explicit L11^{-1} (unit-lower, multipliers in sA) ----
            if (lane < 16) {
                int c = lane;
                float x[16];
#pragma unroll
                for (int j = 0; j < 16; ++j) {
                    float s = 0.f;
#pragma unroll
                    for (int k = 0; k < 16; ++k)
                        if (k < j) s += sA[(c0 + j) * STRIDE + c0 + k] * x[k];
                    x[j] = (j == c) ? 1.f : ((j < c) ? 0.f : -s);
                }
#pragma unroll
                for (int j = 0; j < 16; ++j) sL11inv[j * 16 + c] = x[j];
            }
        }
        __syncthreads();
        // ---- GEMM1 (TRSM): U12 = L11inv @ A12(original), 4 rows/thread, 1 op/thread ----
        float4 acc1[4];
        int m1 = tid;
        bool act1 = (m1 < 4 * tw);
        int i4 = 0, col1 = 0;
        if (act1) {
            i4 = m1 / tw;
            col1 = (g0 + (m1 - i4 * tw)) << 2;
#pragma unroll
            for (int q = 0; q < 4; ++q) acc1[q] = make_float4(0.f, 0.f, 0.f, 0.f);
#pragma unroll 1
            for (int k = 0; k < 16; ++k) {
                const float4 b = *(const float4*)(sA + (c0 + k) * STRIDE + col1);
#pragma unroll
                for (int q = 0; q < 4; ++q) {
                    float f = sL11inv[(i4 * 4 + q) * 16 + k];
                    acc1[q].x += f * b.x; acc1[q].y += f * b.y;
                    acc1[q].z += f * b.z; acc1[q].w += f * b.w;
                }
            }
        }
        __syncthreads();
        if (act1) {
#pragma unroll
            for (int q = 0; q < 4; ++q)
                *(float4*)(sA + (c0 + i4 * 4 + q) * STRIDE + col1) = acc1[q];
        }
        __syncthreads();
        // ---- GEMM2: A22 -= L21 @ U12 (rank 16), 4 rows/thread ----
        int rs = c0 + 16, nr = 64 - rs;
        int nq = nr >> 2;
        for (int m = tid; m < nq * tw; m += bs) {
            int q4 = m / tw, gg = m - q4 * tw;
            int r = rs + q4 * 4;
            int col = (g0 + gg) << 2;
            float4 a0 = *(const float4*)(sA + (r + 0) * STRIDE + col);
            float4 a1 = *(const float4*)(sA + (r + 1) * STRIDE + col);
            float4 a2 = *(const float4*)(sA + (r + 2) * STRIDE + col);
            float4 a3 = *(const float4*)(sA + (r + 3) * STRIDE + col);
#pragma unroll 1
            for (int k = 0; k < 16; ++k) {
                const float4 b = *(const float4*)(sA + (c0 + k) * STRIDE + col);
                float f0 = sA[(r + 0) * STRIDE + c0 + k];
                float f1 = sA[(r + 1) * STRIDE + c0 + k];
                float f2 = sA[(r + 2) * STRIDE + c0 + k];
                float f3 = sA[(r + 3) * STRIDE + c0 + k];
                a0.x -= f0 * b.x; a0.y -= f0 * b.y; a0.z -= f0 * b.z; a0.w -= f0 * b.w;
                a1.x -= f1 * b.x; a1.y -= f1 * b.y; a1.z -= f1 * b.z; a1.w -= f1 * b.w;
                a2.x -= f2 * b.x; a2.y -= f2 * b.y; a2.z -= f2 * b.z; a2.w -= f2 * b.w;
                a3.x -= f3 * b.x; a3.y -= f3 * b.y; a3.z -= f3 * b.z; a3.w -= f3 * b.w;
            }
            *(float4*)(sA + (r + 0) * STRIDE + col) = a0;
            *(float4*)(sA + (r + 1) * STRIDE + col) = a1;
            *(float4*)(sA + (r + 2) * STRIDE + col) = a2;
            *(float4*)(sA + (r + 3) * STRIDE + col) = a3;
        }
        __syncthreads();
    }
}

// ---------------- shared epilogue: precise inv, scaled RHS, score pieces ----------------
__device__ __forceinline__ void pivot_epilogue2(const float* sA, int stride, int dcol,
                                                float* sInv, float* sTv, float* sRed, int tid) {
    float val = 0.f;
    if (tid < 64) {
        float piv = sA[tid * stride + tid];
        float iv = 1.0f / piv;
        sInv[tid] = iv;
        float y = sA[tid * stride + dcol];
        sTv[tid] = y * iv;
        val = logf(piv) + y * y * iv;
    }
    for (int o = 16; o > 0; o >>= 1) val += __shfl_down_sync(~0u, val, o);
    if (tid == 0) sRed[0] = val;
    if (tid == 32) sRed[1] = val;
}

// ---------------- Schur 32x32 warp tile: thread = 4 rows x 8 cols ----------------
__device__ __forceinline__ void schur_tile32(const float* sA, const float* sInv, int stride,
                                             int wb, int i0, int j0, int lane,
                                             float acc[4][8]) {
    int ra = wb + i0 + (lane & 7) * 4;
    int cb = wb + j0 + (lane >> 3) * 8;
#pragma unroll
    for (int q = 0; q < 4; q++)
#pragma unroll
        for (int w = 0; w < 8; w++) acc[q][w] = 0.f;
#pragma unroll 1
    for (int k = 0; k < 64; ++k) {
        const float* row = sA + k * stride;
        float iv = sInv[k];
        float4 av = *(const float4*)(row + ra);
        float4 b0 = *(const float4*)(row + cb);
        float4 b1 = *(const float4*)(row + cb + 4);
        float a[4] = {av.x * iv, av.y * iv, av.z * iv, av.w * iv};
        float b[8] = {b0.x, b0.y, b0.z, b0.w, b1.x, b1.y, b1.z, b1.w};
#pragma unroll
        for (int q = 0; q < 4; q++)
#pragma unroll
            for (int w = 0; w < 8; w++) acc[q][w] += a[q] * b[w];
    }
}

// write direct (and optionally mirrored, coalesced) 32x32 tile of values in acc
__device__ __forceinline__ void store_tile(float* sig, const float acc[4][8],
                                           int i0, int j0, int lane, bool mirror) {
    int rbase = i0 + (lane & 7) * 4;
    int cb = j0 + (lane >> 3) * 8;
#pragma unroll
    for (int q = 0; q < 4; ++q) {
        float4 v0 = {acc[q][0], acc[q][1], acc[q][2], acc[q][3]};
        float4 v1 = {acc[q][4], acc[q][5], acc[q][6], acc[q][7]};
        *(float4*)(sig + (rbase + q) * 128 + cb) = v0;
        *(float4*)(sig + (rbase + q) * 128 + cb + 4) = v1;
    }
    if (mirror) {
#pragma unroll
        for (int w = 0; w < 8; ++w) {
            float4 mv = {acc[0][w], acc[1][w], acc[2][w], acc[3][w]};
            *(float4*)(sig + (cb + w) * 128 + rbase) = mv;
        }
    }
}

// tile tables: 10 tiles covering symmetric 128x128 (4 diag + 6 strict-lower)
__constant__ int cTI[10] = {0, 1, 2, 3, 1, 3, 2, 3, 2, 3};
__constant__ int cTJ[10] = {0, 1, 2, 3, 0, 2, 0, 0, 1, 1};

// ---------------- leaf: h_t = N(x; im_t, D_t) * N([x;z]; tmu, Tvar) ----------------
__global__ void __launch_bounds__(NT, 3) leaf_kernel(const int* __restrict__ sent,
                                                     const float* __restrict__ memb,
                                                     const float* __restrict__ cemb,
                                                     const float* __restrict__ tmu) {
    extern __shared__ float sm[];
    float* sA = sm;                     // 64 x STR
    float* sL11inv = sA + 64 * STR;     // 16 x 16
    float* sInv = sL11inv + 256;
    float* sTv = sInv + 64;
    float* sRed = sTv + 64;
    int t = blockIdx.x, tid = threadIdx.x;
    int wid = tid >> 5, lane = tid & 31;
    int tok = sent[t];
    for (int idx = tid; idx < 64 * 128; idx += NT) {
        int r = idx >> 7, c = idx & 127;
        float v = gTvar[r * 128 + c];
        sA[r * STR + 64 + c] = v;              // W = Tvar rows 0..63 (full 128 cols)
        if (c < 64) sA[r * STR + c] = v;       // S = Saa
    }
    __syncthreads();
    if (tid < 64) {
        float ch = cemb[tok * 64 + tid];
        sA[tid * STR + tid] += ch * ch;                           // S = Saa + D
        sA[tid * STR + D_COL] = memb[tok * 64 + tid] - tmu[tid];  // d = im - mu_a
        sA[tid * STR + 193] = 0.f; sA[tid * STR + 194] = 0.f; sA[tid * STR + 195] = 0.f;
    }
    __syncthreads();
    factor_fast<STR, 193>(sA, sL11inv, tid, NT);
    pivot_epilogue2(sA, STR, D_COL, sInv, sTv, sRed, tid);
    __syncthreads();
    float* eo = gBufA + (size_t)t * ELT;
    if (tid < 128) {      // mu' = tmu + W^T D^-1 y
        float a = 0.f;
        for (int k = 0; k < 64; ++k) a += sA[k * STR + 64 + tid] * sTv[k];
        eo[MU_OFF + tid] = tmu[tid] + a;
    }
    if (tid == 128) eo[W_OFF] = -0.5f * (64.f * LOG2PI + sRed[0] + sRed[1]);

    // Sigma' = Tvar - W^T D^-1 W : symmetric, 10 tiles (4 diag + 6 lower+mirror)
    for (int tt = wid; tt < 10; tt += 8) {
        int i0 = cTI[tt] * 32, j0 = cTJ[tt] * 32;
        float acc[4][8];
        schur_tile32(sA, sInv, STR, 64, i0, j0, lane, acc);
        int rbase = i0 + (lane & 7) * 4;
        int cb = j0 + (lane >> 3) * 8;
#pragma unroll
        for (int q = 0; q < 4; ++q)
#pragma unroll
            for (int w = 0; w < 8; ++w)
                acc[q][w] = gTvar[(rbase + q) * 128 + cb + w] - acc[q][w];
        store_tile(eo + SIG_OFF, acc, i0, j0, lane, tt >= 4);
    }
}

// ---------------- shared compose body ----------------
__device__ __forceinline__ void compose_body(const float* __restrict__ e1,
                                             const float* __restrict__ e2,
                                             float* __restrict__ eo,
                                             float* sm, int tid, int bs) {
    float* sA = sm;
    float* sL11inv = sA + 64 * STR;
    float* sInv = sL11inv + 256;
    float* sTv = sInv + 64;
    float* sRed = sTv + 64;
    int wid = tid >> 5, lane = tid & 31, nw = bs >> 5;
    const float* S1 = e1 + SIG_OFF;
    const float* S2 = e2 + SIG_OFF;
    for (int idx = tid; idx < 64 * 64; idx += bs) {
        int r = idx >> 6, c = idx & 63;
        sA[r * STR + c] = S1[(64 + r) * 128 + 64 + c] + S2[r * 128 + c];  // P_yy + Q_yy
        sA[r * STR + 64 + c] = S1[(64 + r) * 128 + c];                     // P_yx
        sA[r * STR + 128 + c] = S2[r * 128 + 64 + c];                      // Q_yz
    }
    if (tid < 64) {
        sA[tid * STR + D_COL] = e1[MU_OFF + 64 + tid] - e2[MU_OFF + tid];  // d
        sA[tid * STR + 193] = 0.f; sA[tid * STR + 194] = 0.f; sA[tid * STR + 195] = 0.f;
    }
    __syncthreads();
    factor_fast<STR, 193>(sA, sL11inv, tid, bs);
    pivot_epilogue2(sA, STR, D_COL, sInv, sTv, sRed, tid);
    __syncthreads();
    if (tid < 64) {        // mu'_x = m1_x - W_P^T D^-1 y
        float a = 0.f;
        for (int k = 0; k < 64; ++k) a += sA[k * STR + 64 + tid] * sTv[k];
        eo[MU_OFF + tid] = e1[MU_OFF + tid] - a;
    } else if (tid < 128) { // mu'_z = m2_z + W_Q^T D^-1 y
        int cc = tid - 64;
        float a = 0.f;
        for (int k = 0; k < 64; ++k) a += sA[k * STR + 128 + cc] * sTv[k];
        eo[MU_OFF + tid] = e2[MU_OFF + 64 + cc] + a;
    }
    if (tid == 128)
        eo[W_OFF] = e1[W_OFF] + e2[W_OFF] - 0.5f * (64.f * LOG2PI + sRed[0] + sRed[1]);

    // Sigma' symmetric 128x128: 10 tiles; quadrant picks base (S1 / S2 / +acc)
    for (int tt = wid; tt < 10; tt += nw) {
        int i0 = cTI[tt] * 32, j0 = cTJ[tt] * 32;
        float acc[4][8];
        schur_tile32(sA, sInv, STR, 64, i0, j0, lane, acc);
        int rbase = i0 + (lane & 7) * 4;
        int cb = j0 + (lane >> 3) * 8;
        bool rLow = (i0 < 64), cLow = (j0 < 64);
        if (rLow && cLow) {
#pragma unroll
            for (int q = 0; q < 4; ++q)
#pragma unroll
                for (int w = 0; w < 8; ++w)
                    acc[q][w] = S1[(rbase + q) * 128 + cb + w] - acc[q][w];
        } else if (!rLow && !cLow) {
#pragma unroll
            for (int q = 0; q < 4; ++q)
#pragma unroll
                for (int w = 0; w < 8; ++w)
                    acc[q][w] = S2[(rbase + q) * 128 + cb + w] - acc[q][w];
        }
        // mixed quadrant: Sigma'_zx = +W_Q^T D^-1 W_P = acc as-is
        store_tile(eo + SIG_OFF, acc, i0, j0, lane, tt >= 4);
    }
}

// wide levels: 256 threads, min 3 CTAs/SM
__global__ void __launch_bounds__(NT, 3) compose_wide_kernel(const float* __restrict__ e1b,
                                                             const float* __restrict__ e2b,
                                                             float* __restrict__ eob) {
    extern __shared__ float sm[];
    const float* e1 = e1b + (size_t)blockIdx.x * (size_t)(2 * ELT);
    const float* e2 = e1 + ELT;
    float* eo = eob + (size_t)blockIdx.x * (size_t)ELT;
    compose_body(e1, e2, eo, sm, threadIdx.x, NT);
}

// tail levels: 512 threads (occupancy irrelevant, latency matters)
__global__ void __launch_bounds__(512) compose_tail_kernel(const float* __restrict__ e1b,
                                                           const float* __restrict__ e2b,
                                                           float* __restrict__ eob,
                                                           long sIn, long sOut) {
    extern __shared__ float sm[];
    const float* e1 = e1b + (size_t)blockIdx.x * (size_t)sIn;
    const float* e2 = e2b + (size_t)blockIdx.x * (size_t)sIn;
    float* eo = eob + (size_t)blockIdx.x * (size_t)sOut;
    compose_body(e1, e2, eo, sm, threadIdx.x, blockDim.x);
}

// ---------------- z-only final compose: only logw, mu_z, Sigma_zz of eI (.) root ----------------
__global__ void __launch_bounds__(512) compose_z_kernel(const float* __restrict__ e1,
                                                        const float* __restrict__ e2,
                                                        float* __restrict__ eo) {
    extern __shared__ float sm[];
    float* sA = sm;                      // 64 x STRZ : [S(64) | Wq(64) | d | pad]
    float* sL11inv = sA + 64 * STRZ;
    float* sInv = sL11inv + 256;
    float* sTv = sInv + 64;
    float* sRed = sTv + 64;
    int tid = threadIdx.x, bs = blockDim.x;
    int wid = tid >> 5, lane = tid & 31, nw = bs >> 5;
    const float* S1 = e1 + SIG_OFF;
    const float* S2 = e2 + SIG_OFF;
    for (int idx = tid; idx < 64 * 64; idx += bs) {
        int r = idx >> 6, c = idx & 63;
        sA[r * STRZ + c] = S1[(64 + r) * 128 + 64 + c] + S2[r * 128 + c];  // P_yy + Q_yy
        sA[r * STRZ + 64 + c] = S2[r * 128 + 64 + c];                       // Q_yz
    }
    if (tid < 64) {
        sA[tid * STRZ + D_COLZ] = e1[MU_OFF + 64 + tid] - e2[MU_OFF + tid];
        sA[tid * STRZ + 129] = 0.f; sA[tid * STRZ + 130] = 0.f; sA[tid * STRZ + 131] = 0.f;
    }
    __syncthreads();
    factor_fast<STRZ, 129>(sA, sL11inv, tid, bs);
    pivot_epilogue2(sA, STRZ, D_COLZ, sInv, sTv, sRed, tid);
    __syncthreads();
    if (tid < 64) {        // mu'_z = m2_z + W_Q^T D^-1 y
        float a = 0.f;
        for (int k = 0; k < 64; ++k) a += sA[k * STRZ + 64 + tid] * sTv[k];
        eo[MU_OFF + 64 + tid] = e2[MU_OFF + 64 + tid] + a;
    }
    if (tid == 64)
        eo[W_OFF] = e1[W_OFF] + e2[W_OFF] - 0.5f * (64.f * LOG2PI + sRed[0] + sRed[1]);
    // Sigma'_zz = S2_zz - Wq^T D^-1 Wq (64x64 symmetric): 3 tiles (2 diag + 1 lower)
    for (int tt = wid; tt < 3; tt += nw) {
        int i0 = (tt == 1) ? 32 : ((tt == 2) ? 32 : 0);
        int j0 = (tt == 1) ? 32 : 0;
        float acc[4][8];
        schur_tile32(sA, sInv, STRZ, 64, i0, j0, lane, acc);
        int rbase = i0 + (lane & 7) * 4;
        int cb = j0 + (lane >> 3) * 8;
#pragma unroll
        for (int q = 0; q < 4; ++q)
#pragma unroll
            for (int w = 0; w < 8; ++w)
                acc[q][w] = S2[(64 + rbase + q) * 128 + 64 + cb + w] - acc[q][w];
        // write into the zz quadrant of eo's Sigma
        float* sig = eo + SIG_OFF + 64 * 128 + 64;
        int rb = rbase, cc = cb;
#pragma unroll
        for (int q = 0; q < 4; ++q) {
            float4 v0 = {acc[q][0], acc[q][1], acc[q][2], acc[q][3]};
            float4 v1 = {acc[q][4], acc[q][5], acc[q][6], acc[q][7]};
            *(float4*)(sig + (rb + q) * 128 + cc) = v0;
            *(float4*)(sig + (rb + q) * 128 + cc + 4) = v1;
        }
        if (tt == 2) {
#pragma unroll
            for (int w = 0; w < 8; ++w) {
                float4 mv = {acc[0][w], acc[1][w], acc[2][w], acc[3][w]};
                *(float4*)(sig + (cc + w) * 128 + rb) = mv;
            }
        }
    }
}

// ---------------- decode: 50 independent scores via the same fast factor ----------------
#define DSTR 68
__global__ void __launch_bounds__(NT) decode_kernel(const float* __restrict__ omu,
                                                    const float* __restrict__ ocho,
                                                    float* __restrict__ out, int nlab) {
    extern __shared__ float sm[];
    float* sA = sm;                    // 64 x DSTR, cols: S(64) | z(1) | pad
    float* sL11inv = sA + 64 * DSTR;
    float* sRed = sL11inv + 256;
    int l = blockIdx.x, tid = threadIdx.x;
    if (l >= nlab) return;
    for (int idx = tid; idx < 64 * 64; idx += NT) {
        int r = idx >> 6, c = idx & 63;
        sA[r * DSTR + c] = gFin[SIG_OFF + (64 + r) * 128 + 64 + c];
    }
    __syncthreads();
    if (tid < 64) {
        float oc = ocho[l * 64 + tid];
        sA[tid * DSTR + tid] += oc * oc;
        sA[tid * DSTR + 64] = gFin[MU_OFF + 64 + tid] - omu[l * 64 + tid];
        sA[tid * DSTR + 65] = 0.f; sA[tid * DSTR + 66] = 0.f; sA[tid * DSTR + 67] = 0.f;
    }
    __syncthreads();
    factor_fast<DSTR, 65>(sA, sL11inv, tid, NT);
    float val = 0.f;
    if (tid < 64) {
        float piv = sA[tid * DSTR + tid];
        float y = sA[tid * DSTR + 64];
        val = logf(piv) + y * y / piv;
    }
    for (int o = 16; o > 0; o >>= 1) val += __shfl_down_sync(~0u, val, o);
    if (tid == 0) sRed[0] = val;
    if (tid == 32) sRed[1] = val;
    __syncthreads();
    if (tid == 0) out[l] = gFin[W_OFF] - 0.5f * (64.f * LOG2PI + sRed[0] + sRed[1]);
}

// ---------------- launch ----------------
static const int CSM  = (64 * STR + 256 + 64 + 64 + 8) * 4;
static const int CSMZ = (64 * STRZ + 256 + 64 + 64 + 8) * 4;
static const int DSM  = (64 * DSTR + 256 + 8) * 4;

extern "C" void kernel_launch(void* const* d_in, const int* in_sizes, int n_in,
                              void* d_out, int out_size) {
    const int*   sent = (const int*)d_in[0];
    const float* memb = (const float*)d_in[2];
    const float* cemb = (const float*)d_in[3];
    const float* tmu  = (const float*)d_in[4];
    const float* tcho = (const float*)d_in[5];
    const float* omu  = (const float*)d_in[6];
    const float* ocho = (const float*)d_in[7];
    float* out = (float*)d_out;

    int n = in_sizes[0];
    if (n > TMAX) n = TMAX;
    if (n < 1) n = 1;
    int nlab = out_size;
    if (nlab <= 0) nlab = in_sizes[6] / 64;

    cudaFuncSetAttribute(prek_kernel, cudaFuncAttributeMaxDynamicSharedMemorySize, 128 * 128 * 4);
    cudaFuncSetAttribute(leaf_kernel, cudaFuncAttributeMaxDynamicSharedMemorySize, CSM);
    cudaFuncSetAttribute(compose_wide_kernel, cudaFuncAttributeMaxDynamicSharedMemorySize, CSM);
    cudaFuncSetAttribute(compose_tail_kernel, cudaFuncAttributeMaxDynamicSharedMemorySize, CSM);
    cudaFuncSetAttribute(compose_z_kernel, cudaFuncAttributeMaxDynamicSharedMemorySize, CSMZ);
    cudaFuncSetAttribute(decode_kernel, cudaFuncAttributeMaxDynamicSharedMemorySize, DSM);

    float *bufA, *bufB, *eP, *eG, *eI, *fin;
    cudaGetSymbolAddress((void**)&bufA, gBufA);
    cudaGetSymbolAddress((void**)&bufB, gBufB);
    cudaGetSymbolAddress((void**)&eP, gEP);
    cudaGetSymbolAddress((void**)&eG, gEG);
    cudaGetSymbolAddress((void**)&eI, gEI);
    cudaGetSymbolAddress((void**)&fin, gFin);

    prek_kernel<<<1, NT, 128 * 128 * 4>>>(tcho);
    einit_kernel<<<1, NT>>>(tmu);
    compose_tail_kernel<<<1, 512, CSM>>>(eP, eG, eI, 0, 0);    // eInit = prior (.) joint
    leaf_kernel<<<n, NT, CSM>>>(sent, memb, cemb, tmu);

    float* src = bufA;
    float* dst = bufB;
    int m = n;
    while (m > 1) {
        int nc = m >> 1;
        if (nc > 148)
            compose_wide_kernel<<<nc, NT, CSM>>>(src, src + ELT, dst);
        else
            compose_tail_kernel<<<nc, 512, CSM>>>(src, src + ELT, dst,
                                                  (long)(2 * ELT), (long)ELT);
        if (m & 1)
            cudaMemcpyAsync(dst + (size_t)nc * ELT, src + (size_t)(m - 1) * ELT,
                            (size_t)ELT * sizeof(float), cudaMemcpyDeviceToDevice);
        m = (m + 1) >> 1;
        float* tp = src; src = dst; dst = tp;
    }
    compose_z_kernel<<<1, 512, CSMZ>>>(eI, src, fin);
    decode_kernel<<<nlab, NT, DSM>>>(omu, ocho, out, nlab);
}